// round 9
// baseline (speedup 1.0000x reference)
#include <cuda_runtime.h>
#include <cuda_bf16.h>

// ArcFaceLoss: N=8192 rows, C=32000 classes, fp32 pred, int target.
// loss_i = lse(logits_i) - S*margin(c_t)   where logits = 30*clamp(pred,-1,1),
// with the target column replaced by the arcface margin value.
//
// Fused single-launch design, v2:
//  - clamp bounds logits to [-30,30] -> fixed softmax max -> one streaming
//    pass computes sum(exp(30c-30)); target column patched as a rank-1
//    correction (one extra scalar load, L2-hit).
//  - dtype sniff (int64 vs int32 targets): warp 0 only, 32 high words.
//  - final mean via last-block pattern using a RELEASE atomic (no
//    __threadfence -> no per-block MEMBAR.GPU/CCTL.IVALL L1 flush, which cost
//    ~7us across 8192 blocks in R8). Tail reads via __ldcg (L2-direct).
//    Counter self-resets for graph replay; fixed-order sums -> deterministic.

#define N_ROWS 8192
#define C_COLS 32000

__device__ float g_row_loss[N_ROWS];
__device__ unsigned int g_done = 0;

// M = 0.5
#define COS_M      0.877582561890373f
#define SIN_M      0.479425538604203f
#define MM_CONST   0.239712769302101f     // sin(0.5)*0.5
#define THRESH    -0.877582561890373f     // -cos(0.5)
#define S_SCALE    30.0f
#define K2         43.28085122666891f     // 30*log2(e)

__device__ __forceinline__ float clamp1(float x) {
    return fminf(fmaxf(x, -1.0f), 1.0f);
}

__device__ __forceinline__ float eterm(float c) {
    // exp(30*c - 30) == exp2(K2*c - K2)
    return exp2f(fmaf(K2, c, -K2));
}

__global__ __launch_bounds__(256) void arcface_kernel(
    const float* __restrict__ pred,
    const void*  __restrict__ tgt,
    float* __restrict__ out)
{
    const int row = blockIdx.x;
    const int tid = threadIdx.x;

    __shared__ float warp_part[8];
    __shared__ unsigned sniff;
    __shared__ bool is_last;

    // ---- dtype sniff: warp 0 checks 32 high words -------------------------
    // int64 targets (< 32000) have all-zero high words; 32 random int32
    // targets all being zero has prob ~(1/32000)^32. In-bounds for both
    // interpretations (int indices 1..63 < 8192).
    if (tid < 32) {
        int hi = reinterpret_cast<const int*>(tgt)[2 * tid + 1];
        unsigned nz = __ballot_sync(0xFFFFFFFFu, hi != 0);
        if (tid == 0) { sniff = nz; is_last = false; }
    }

    // ---- streaming sum(exp(30*clamp(x)-30)) over this row -----------------
    const float4* __restrict__ p =
        reinterpret_cast<const float4*>(pred + (size_t)row * C_COLS);

    float s0 = 0.0f, s1 = 0.0f;
    #pragma unroll 4
    for (int i = tid; i < C_COLS / 4; i += 256) {
        float4 v = __ldcs(&p[i]);
        s0 += eterm(clamp1(v.x)) + eterm(clamp1(v.y));
        s1 += eterm(clamp1(v.z)) + eterm(clamp1(v.w));
    }
    float s = s0 + s1;

    #pragma unroll
    for (int off = 16; off > 0; off >>= 1)
        s += __shfl_down_sync(0xFFFFFFFFu, s, off);
    if ((tid & 31) == 0) warp_part[tid >> 5] = s;
    __syncthreads();

    if (tid == 0) {
        float total = 0.0f;
        #pragma unroll
        for (int w = 0; w < 8; w++) total += warp_part[w];

        // target index (dtype-robust)
        long long t;
        if (sniff == 0u)
            t = reinterpret_cast<const long long*>(tgt)[row];
        else
            t = reinterpret_cast<const int*>(tgt)[row];

        float c = clamp1(pred[(size_t)row * C_COLS + t]);

        // arcface margin on the target cosine
        float tm;
        if (c > THRESH) {
            float sn = sqrtf(fmaxf(1.0f - c * c, 0.0f));
            tm = fmaf(c, COS_M, -sn * SIN_M);   // cos(acos(c)+M)
        } else {
            tm = c - MM_CONST;
        }

        // rank-1 correction: swap original target term for margin term
        float sum = total - eterm(c) + eterm(tm);

        // loss = lse - S*tm
        float loss = S_SCALE + logf(sum) - S_SCALE * tm;
        __stcg(&g_row_loss[row], loss);

        // release atomic: orders the L2-visible loss store before the count,
        // WITHOUT a gpu-scope membar / L1D flush.
        unsigned prev;
        asm volatile("atom.add.release.gpu.global.u32 %0, [%1], %2;"
                     : "=r"(prev)
                     : "l"(&g_done), "r"(1u)
                     : "memory");
        is_last = (prev == (unsigned)(gridDim.x - 1));
    }
    __syncthreads();

    // ---- last-block final mean (L2-direct reads, fixed order) -------------
    if (is_last) {
        float acc = 0.0f;
        #pragma unroll
        for (int i = tid; i < N_ROWS; i += 256) acc += __ldcg(&g_row_loss[i]);

        #pragma unroll
        for (int off = 16; off > 0; off >>= 1)
            acc += __shfl_down_sync(0xFFFFFFFFu, acc, off);
        if ((tid & 31) == 0) warp_part[tid >> 5] = acc;
        __syncthreads();

        if (tid == 0) {
            float v = 0.0f;
            #pragma unroll
            for (int w = 0; w < 8; w++) v += warp_part[w];
            out[0] = v * (1.0f / (float)N_ROWS);
            g_done = 0;                    // reset for next graph replay
        }
    }
}

extern "C" void kernel_launch(void* const* d_in, const int* in_sizes, int n_in,
                              void* d_out, int out_size)
{
    const float* pred = (const float*)d_in[0];
    const void*  tgt  = d_in[1];
    float* out = (float*)d_out;

    arcface_kernel<<<N_ROWS, 256>>>(pred, tgt, out);
}

// round 10
// speedup vs baseline: 1.0580x; 1.0580x over previous
#include <cuda_runtime.h>
#include <cuda_bf16.h>

// ArcFaceLoss: N=8192 rows, C=32000 classes, fp32 pred, int target.
// loss_i = lse(logits_i) - S*margin(c_t)   where logits = 30*clamp(pred,-1,1),
// with the target column replaced by the arcface margin value.
//
// Two-launch design (fused single-launch variants measured SLOWER in R8/R9):
//  - row kernel: dtype sniff inlined (warp 0, 32 high words, overlaps with
//    stream start), one streaming pass of sum(exp(30c-30)) at ~7.3 TB/s,
//    target column patched as a rank-1 correction.
//  - separate tiny reduce kernel for the final mean (inter-kernel ordering
//    gives visibility; no atomics/fences in the hot kernel).

#define N_ROWS 8192
#define C_COLS 32000

__device__ float g_row_loss[N_ROWS];

// M = 0.5
#define COS_M      0.877582561890373f
#define SIN_M      0.479425538604203f
#define MM_CONST   0.239712769302101f     // sin(0.5)*0.5
#define THRESH    -0.877582561890373f     // -cos(0.5)
#define S_SCALE    30.0f
#define K2         43.28085122666891f     // 30*log2(e)

__device__ __forceinline__ float clamp1(float x) {
    return fminf(fmaxf(x, -1.0f), 1.0f);
}

__device__ __forceinline__ float eterm(float c) {
    // exp(30*c - 30) == exp2(K2*c - K2)
    return exp2f(fmaf(K2, c, -K2));
}

// ---------------------------------------------------------------------------
// Kernel 1: one block per row. Warp 0 sniffs target dtype (int64 targets
// < 32000 have all-zero high words; 32 random int32 targets all zero has
// prob ~(1/32000)^32 ~ 0). All 256 threads stream 8000 float4 and accumulate
// sum(exp(30*clamp(x)-30)); block-reduce; thread 0 applies the target-column
// margin correction and writes the per-row loss.
__global__ __launch_bounds__(256) void row_loss_kernel(
    const float* __restrict__ pred,
    const void*  __restrict__ tgt)
{
    const int row = blockIdx.x;
    const int tid = threadIdx.x;

    __shared__ float warp_part[8];
    __shared__ unsigned sniff;

    // dtype sniff: warp 0 only; in-bounds under both interpretations
    // (int indices 1..63 < 8192). L1/L2 hits after the first wave.
    if (tid < 32) {
        int hi = reinterpret_cast<const int*>(tgt)[2 * tid + 1];
        unsigned nz = __ballot_sync(0xFFFFFFFFu, hi != 0);
        if (tid == 0) sniff = nz;
    }

    // streaming sum over this row: 32000/4 = 8000 float4
    const float4* __restrict__ p =
        reinterpret_cast<const float4*>(pred + (size_t)row * C_COLS);

    float s0 = 0.0f, s1 = 0.0f;
    #pragma unroll 4
    for (int i = tid; i < C_COLS / 4; i += 256) {
        float4 v = __ldcs(&p[i]);
        s0 += eterm(clamp1(v.x)) + eterm(clamp1(v.y));
        s1 += eterm(clamp1(v.z)) + eterm(clamp1(v.w));
    }
    float s = s0 + s1;

    // block reduction: warp shuffle + smem
    #pragma unroll
    for (int off = 16; off > 0; off >>= 1)
        s += __shfl_down_sync(0xFFFFFFFFu, s, off);
    if ((tid & 31) == 0) warp_part[tid >> 5] = s;
    __syncthreads();

    if (tid == 0) {
        float total = 0.0f;
        #pragma unroll
        for (int w = 0; w < 8; w++) total += warp_part[w];

        // target index (dtype-robust)
        long long t;
        if (sniff == 0u)
            t = reinterpret_cast<const long long*>(tgt)[row];
        else
            t = reinterpret_cast<const int*>(tgt)[row];

        float c = clamp1(pred[(size_t)row * C_COLS + t]);

        // arcface margin on the target cosine
        float tm;
        if (c > THRESH) {
            float sn = sqrtf(fmaxf(1.0f - c * c, 0.0f));
            tm = fmaf(c, COS_M, -sn * SIN_M);   // cos(acos(c)+M)
        } else {
            tm = c - MM_CONST;
        }

        // rank-1 correction: swap original target term for margin term
        float sum = total - eterm(c) + eterm(tm);

        // loss = lse - S*tm = (S + log(sum)) - S*tm
        g_row_loss[row] = S_SCALE + logf(sum) - S_SCALE * tm;
    }
}

// ---------------------------------------------------------------------------
// Kernel 2: mean of the 8192 row losses -> d_out[0]
__global__ __launch_bounds__(1024) void reduce_kernel(float* __restrict__ out) {
    const int tid = threadIdx.x;
    float s = 0.0f;
    #pragma unroll
    for (int i = tid; i < N_ROWS; i += 1024) s += g_row_loss[i];

    __shared__ float warp_part[32];
    #pragma unroll
    for (int off = 16; off > 0; off >>= 1)
        s += __shfl_down_sync(0xFFFFFFFFu, s, off);
    if ((tid & 31) == 0) warp_part[tid >> 5] = s;
    __syncthreads();

    if (tid < 32) {
        float v = warp_part[tid];
        #pragma unroll
        for (int off = 16; off > 0; off >>= 1)
            v += __shfl_down_sync(0xFFFFFFFFu, v, off);
        if (tid == 0) out[0] = v * (1.0f / (float)N_ROWS);
    }
}

// ---------------------------------------------------------------------------
extern "C" void kernel_launch(void* const* d_in, const int* in_sizes, int n_in,
                              void* d_out, int out_size)
{
    const float* pred = (const float*)d_in[0];
    const void*  tgt  = d_in[1];
    float* out = (float*)d_out;

    row_loss_kernel<<<N_ROWS, 256>>>(pred, tgt);
    reduce_kernel<<<1, 1024>>>(out);
}